// round 1
// baseline (speedup 1.0000x reference)
#include <cuda_runtime.h>
#include <cuda_bf16.h>
#include <mma.h>
#include <cstdint>

using namespace nvcuda;

// Problem dims (fixed by the dataset)
#define NUM_E 16
#define NTOK  2048
#define DDIM  1024
#define HDIM  4096

// Scratch for the hidden activations (allocation-free rule: __device__ global)
__device__ float g_hidden[(size_t)NUM_E * NTOK * HDIM];

// Tiling
constexpr int BM = 128, BN = 128, BK = 32;
constexpr int LDA_S = BK + 8;   // 40  (bf16 elems) -> conflict-free LDSM
constexpr int LDB_S = BN + 8;   // 136

// ---------------------------------------------------------------------------
// Split-bf16 GEMM:  C[e] = A[e] (MxK, row-major) @ B[e] (KxN, row-major)
// fp32 operands are split into bf16 hi/lo during smem staging; 3 MMAs per
// k-step recover ~fp32 accuracy (missing lo*lo term ~2^-18 relative).
// Requires M%128==0, N%128==0, K%32==0 (true for all calls here).
// ---------------------------------------------------------------------------
__global__ __launch_bounds__(256) void gemm_bf16split(
    const float* __restrict__ A, const float* __restrict__ B,
    float* __restrict__ C, int M, int N, int K)
{
    __shared__ __nv_bfloat16 Ah[BM][LDA_S];
    __shared__ __nv_bfloat16 Al[BM][LDA_S];
    __shared__ __nv_bfloat16 Bh[BK][LDB_S];
    __shared__ __nv_bfloat16 Bl[BK][LDB_S];

    const int e = blockIdx.z;
    const float* Ae = A + (size_t)e * M * K;
    const float* Be = B + (size_t)e * K * N;
    float*       Ce = C + (size_t)e * M * N;

    const int tid  = threadIdx.x;
    const int warp = tid >> 5;
    const int wm   = warp >> 2;   // 0..1
    const int wn   = warp & 3;    // 0..3

    const int row0 = blockIdx.y * BM;
    const int col0 = blockIdx.x * BN;

    wmma::fragment<wmma::accumulator, 16, 16, 16, float> acc[4][2];
    #pragma unroll
    for (int i = 0; i < 4; i++)
        #pragma unroll
        for (int j = 0; j < 2; j++)
            wmma::fill_fragment(acc[i][j], 0.0f);

    for (int k0 = 0; k0 < K; k0 += BK) {
        // ---- stage A tile: 128 x 32 fp32 -> hi/lo bf16 (1024 float4, 4/thread)
        #pragma unroll
        for (int i = 0; i < 4; i++) {
            int idx = tid + i * 256;
            int r   = idx >> 3;
            int c4  = (idx & 7) * 4;
            float4 v = *reinterpret_cast<const float4*>(
                Ae + (size_t)(row0 + r) * K + k0 + c4);
            float vv[4] = {v.x, v.y, v.z, v.w};
            #pragma unroll
            for (int q = 0; q < 4; q++) {
                __nv_bfloat16 h = __float2bfloat16(vv[q]);
                Ah[r][c4 + q] = h;
                Al[r][c4 + q] = __float2bfloat16(vv[q] - __bfloat162float(h));
            }
        }
        // ---- stage B tile: 32 x 128 fp32 -> hi/lo bf16
        #pragma unroll
        for (int i = 0; i < 4; i++) {
            int idx = tid + i * 256;
            int r   = idx >> 5;
            int c4  = (idx & 31) * 4;
            float4 v = *reinterpret_cast<const float4*>(
                Be + (size_t)(k0 + r) * N + col0 + c4);
            float vv[4] = {v.x, v.y, v.z, v.w};
            #pragma unroll
            for (int q = 0; q < 4; q++) {
                __nv_bfloat16 h = __float2bfloat16(vv[q]);
                Bh[r][c4 + q] = h;
                Bl[r][c4 + q] = __float2bfloat16(vv[q] - __bfloat162float(h));
            }
        }
        __syncthreads();

        #pragma unroll
        for (int kk = 0; kk < BK; kk += 16) {
            wmma::fragment<wmma::matrix_a, 16, 16, 16, __nv_bfloat16, wmma::row_major> ah[4], al[4];
            wmma::fragment<wmma::matrix_b, 16, 16, 16, __nv_bfloat16, wmma::row_major> bh[2], bl[2];
            #pragma unroll
            for (int mi = 0; mi < 4; mi++) {
                wmma::load_matrix_sync(ah[mi], &Ah[wm * 64 + mi * 16][kk], LDA_S);
                wmma::load_matrix_sync(al[mi], &Al[wm * 64 + mi * 16][kk], LDA_S);
            }
            #pragma unroll
            for (int ni = 0; ni < 2; ni++) {
                wmma::load_matrix_sync(bh[ni], &Bh[kk][wn * 32 + ni * 16], LDB_S);
                wmma::load_matrix_sync(bl[ni], &Bl[kk][wn * 32 + ni * 16], LDB_S);
            }
            #pragma unroll
            for (int mi = 0; mi < 4; mi++)
                #pragma unroll
                for (int ni = 0; ni < 2; ni++) {
                    wmma::mma_sync(acc[mi][ni], ah[mi], bh[ni], acc[mi][ni]);
                    wmma::mma_sync(acc[mi][ni], ah[mi], bl[ni], acc[mi][ni]);
                    wmma::mma_sync(acc[mi][ni], al[mi], bh[ni], acc[mi][ni]);
                }
        }
        __syncthreads();
    }

    // ---- epilogue: store raw fp32 accumulators to global
    #pragma unroll
    for (int mi = 0; mi < 4; mi++)
        #pragma unroll
        for (int ni = 0; ni < 2; ni++) {
            float* p = Ce + (size_t)(row0 + wm * 64 + mi * 16) * N
                          + col0 + wn * 32 + ni * 16;
            wmma::store_matrix_sync(p, acc[mi][ni], N, wmma::mem_row_major);
        }
}

// ---------------------------------------------------------------------------
// Elementwise: h = gelu(h + b1)  (exact erf GELU), vectorized float4
// ---------------------------------------------------------------------------
__device__ __forceinline__ float gelu_exact(float v) {
    return 0.5f * v * (1.0f + erff(v * 0.70710678118654752440f));
}

__global__ __launch_bounds__(256) void bias_gelu_kernel(
    float* __restrict__ h, const float* __restrict__ b, size_t n4, int colMask)
{
    size_t i = (size_t)blockIdx.x * blockDim.x + threadIdx.x;
    if (i >= n4) return;
    float4 v = reinterpret_cast<float4*>(h)[i];
    int c = (int)((i * 4) & (size_t)colMask);
    v.x = gelu_exact(v.x + b[c + 0]);
    v.y = gelu_exact(v.y + b[c + 1]);
    v.z = gelu_exact(v.z + b[c + 2]);
    v.w = gelu_exact(v.w + b[c + 3]);
    reinterpret_cast<float4*>(h)[i] = v;
}

__global__ __launch_bounds__(256) void bias_add_kernel(
    float* __restrict__ o, const float* __restrict__ b, size_t n4, int colMask)
{
    size_t i = (size_t)blockIdx.x * blockDim.x + threadIdx.x;
    if (i >= n4) return;
    float4 v = reinterpret_cast<float4*>(o)[i];
    int c = (int)((i * 4) & (size_t)colMask);
    v.x += b[c + 0];
    v.y += b[c + 1];
    v.z += b[c + 2];
    v.w += b[c + 3];
    reinterpret_cast<float4*>(o)[i] = v;
}

// ---------------------------------------------------------------------------
// Launch: gemm1 -> bias+gelu -> gemm2 -> bias
// ---------------------------------------------------------------------------
extern "C" void kernel_launch(void* const* d_in, const int* in_sizes, int n_in,
                              void* d_out, int out_size)
{
    const float* x  = (const float*)d_in[0];   // (E, N, D)
    const float* w1 = (const float*)d_in[1];   // (E, D, H)
    const float* w2 = (const float*)d_in[2];   // (E, H, D)
    const float* b1 = (const float*)d_in[3];   // (H,)
    const float* b2 = (const float*)d_in[4];   // (D,)
    float* out = (float*)d_out;                // (E, N, D)

    float* hidden = nullptr;
    cudaGetSymbolAddress((void**)&hidden, g_hidden);

    dim3 blk(256);

    // GEMM1: per expert (2048 x 1024) @ (1024 x 4096) -> hidden
    dim3 g1(HDIM / BN, NTOK / BM, NUM_E);
    gemm_bf16split<<<g1, blk>>>(x, w1, hidden, NTOK, HDIM, DDIM);

    // hidden = gelu(hidden + b1)
    size_t nh4 = (size_t)NUM_E * NTOK * HDIM / 4;
    bias_gelu_kernel<<<(unsigned)((nh4 + 255) / 256), blk>>>(hidden, b1, nh4, HDIM - 1);

    // GEMM2: per expert (2048 x 4096) @ (4096 x 1024) -> out
    dim3 g2(DDIM / BN, NTOK / BM, NUM_E);
    gemm_bf16split<<<g2, blk>>>(hidden, w2, out, NTOK, DDIM, HDIM);

    // out += b2
    size_t no4 = (size_t)NUM_E * NTOK * DDIM / 4;
    bias_add_kernel<<<(unsigned)((no4 + 255) / 256), blk>>>(out, b2, no4, DDIM - 1);
}

// round 3
// speedup vs baseline: 3.9302x; 3.9302x over previous
#include <cuda_runtime.h>
#include <cuda_fp16.h>
#include <mma.h>
#include <cstdint>

using namespace nvcuda;

#define NE 16
#define NT 2048
#define DD 1024
#define HH 4096

// ---------------- scratch (allocation-free rule: __device__ globals) --------
__device__ __half g_xh [(size_t)NE * NT * DD];   // x  fp16, [E][N][D]
__device__ __half g_w1t[(size_t)NE * HH * DD];   // w1 fp16, [E][H][D] (K-major)
__device__ __half g_w2t[(size_t)NE * DD * HH];   // w2 fp16, [E][D][H] (K-major)
__device__ __half g_hid[(size_t)NE * NT * HH];   // hidden fp16, [E][N][H]

// ---------------- GEMM config ----------------------------------------------
constexpr int BM = 128, BN = 128, BK = 64;
constexpr int SST    = 72;                 // smem stride (halfs): 64 data + 8 pad
constexpr int TILE_B = 128 * SST * 2;      // 18432 B per operand tile
constexpr int STG    = 2 * TILE_B;         // 36864 B per stage (A + B)
constexpr int NSTAGE = 4;
constexpr int SMEM_GEMM = NSTAGE * STG + 1024;   // + bias tile

#define CPA(dst, src) asm volatile("cp.async.cg.shared.global [%0], [%1], 16;" :: "r"(dst), "l"(src))
#define CPC()         asm volatile("cp.async.commit_group;" ::: "memory")
#define CPW(n)        asm volatile("cp.async.wait_group %0;" :: "n"(n) : "memory")

__device__ __forceinline__ float gelu_exact(float v) {
    return 0.5f * v * (1.0f + erff(v * 0.70710678118654752440f));
}

// ---------------------------------------------------------------------------
// C[MxN] = A[MxK] @ Bt[NxK]^T   (both operands fp16 K-major, fp32 accum)
// MODE 1: Oh = fp16(gelu(C + bias))     MODE 2: Of = C + bias (fp32)
// ---------------------------------------------------------------------------
template <int MODE>
__global__ void __launch_bounds__(256, 1) gemm_ffn(
    const __half* __restrict__ A, const __half* __restrict__ Bt,
    const float* __restrict__ bias,
    __half* __restrict__ Oh, float* __restrict__ Of,
    int M, int Ntot, int K)
{
    extern __shared__ char smem[];
    const uint32_t sb = (uint32_t)__cvta_generic_to_shared(smem);

    const int tid  = threadIdx.x;
    const int warp = tid >> 5;
    const int wm   = warp >> 1;            // 0..3 -> 32-row slices
    const int wn   = warp & 1;             // 0..1 -> 64-col slices

    const int e  = blockIdx.z;
    const int m0 = blockIdx.y * BM;
    const int n0 = blockIdx.x * BN;

    const __half* Ae = A  + ((size_t)e * M    + m0) * (size_t)K;
    const __half* Be = Bt + ((size_t)e * Ntot + n0) * (size_t)K;

    float* sBias = (float*)(smem + NSTAGE * STG);
    if (tid < 128) sBias[tid] = bias[n0 + tid];

    // per-thread cp.async slots: 256 rows (A:0-127, B:128-255) x 8 x 16B chunks
    const __half* gsrc[8];
    uint32_t      sdst[8];
    #pragma unroll
    for (int j = 0; j < 8; j++) {
        int idx = j * 256 + tid;
        int row = idx >> 3;
        int c   = idx & 7;
        gsrc[j] = (row < 128 ? Ae + (size_t)row * K
                             : Be + (size_t)(row - 128) * K) + c * 8;
        sdst[j] = sb + row * (SST * 2) + c * 16;   // row*144 covers A then B contiguously
    }

    const int NIT = K / BK;

    // prologue: stages 0..2
    #pragma unroll
    for (int s = 0; s < NSTAGE - 1; s++) {
        #pragma unroll
        for (int j = 0; j < 8; j++) CPA(sdst[j] + s * STG, gsrc[j] + s * BK);
        CPC();
    }

    wmma::fragment<wmma::accumulator, 16, 16, 16, float> acc[2][4];
    #pragma unroll
    for (int mi = 0; mi < 2; mi++)
        #pragma unroll
        for (int ni = 0; ni < 4; ni++) wmma::fill_fragment(acc[mi][ni], 0.0f);

    for (int i = 0; i < NIT; i++) {
        CPW(2);
        __syncthreads();

        if (i + NSTAGE - 1 < NIT) {
            #pragma unroll
            for (int j = 0; j < 8; j++)
                CPA(sdst[j] + ((i + NSTAGE - 1) & 3) * STG,
                    gsrc[j] + (size_t)(i + NSTAGE - 1) * BK);
        }
        CPC();   // empty groups in the tail keep wait_group<2> semantics exact

        const __half* As = (const __half*)(smem + (i & 3) * STG);
        const __half* Bs = As + 128 * SST;

        #pragma unroll
        for (int kk = 0; kk < 4; kk++) {
            wmma::fragment<wmma::matrix_a, 16, 16, 16, __half, wmma::row_major> af[2];
            wmma::fragment<wmma::matrix_b, 16, 16, 16, __half, wmma::col_major> bf[4];
            #pragma unroll
            for (int mi = 0; mi < 2; mi++)
                wmma::load_matrix_sync(af[mi], As + (wm * 32 + mi * 16) * SST + kk * 16, SST);
            #pragma unroll
            for (int ni = 0; ni < 4; ni++)
                wmma::load_matrix_sync(bf[ni], Bs + (wn * 64 + ni * 16) * SST + kk * 16, SST);
            #pragma unroll
            for (int mi = 0; mi < 2; mi++)
                #pragma unroll
                for (int ni = 0; ni < 4; ni++)
                    wmma::mma_sync(acc[mi][ni], af[mi], bf[ni], acc[mi][ni]);
        }
    }

    // ---- epilogue: accum -> smem -> (bias[+gelu]) -> global
    __syncthreads();
    float* eb = (float*)smem;              // 128 x 132 fp32 = 67.6 KB (fits)
    #pragma unroll
    for (int mi = 0; mi < 2; mi++)
        #pragma unroll
        for (int ni = 0; ni < 4; ni++)
            wmma::store_matrix_sync(eb + (wm * 32 + mi * 16) * 132 + wn * 64 + ni * 16,
                                    acc[mi][ni], 132, wmma::mem_row_major);
    __syncthreads();

    const int row = tid >> 1;
    const int cb  = (tid & 1) * 64;
    const size_t gbase = ((size_t)e * M + m0 + row) * (size_t)Ntot + n0 + cb;

    #pragma unroll
    for (int c = 0; c < 64; c += 8) {
        float v[8];
        #pragma unroll
        for (int q = 0; q < 8; q++)
            v[q] = eb[row * 132 + cb + c + q] + sBias[cb + c + q];
        if (MODE == 1) {
            __align__(16) __half hv[8];
            #pragma unroll
            for (int q = 0; q < 8; q++) hv[q] = __float2half(gelu_exact(v[q]));
            *(uint4*)(Oh + gbase + c) = *(const uint4*)hv;
        } else {
            *(float4*)(Of + gbase + c)     = make_float4(v[0], v[1], v[2], v[3]);
            *(float4*)(Of + gbase + c + 4) = make_float4(v[4], v[5], v[6], v[7]);
        }
    }
}

// ---------------- preprocessing ---------------------------------------------
__global__ void __launch_bounds__(256) f2h_kernel(
    const float* __restrict__ x, __half* __restrict__ o, size_t n4)
{
    size_t i = (size_t)blockIdx.x * 256 + threadIdx.x;
    if (i >= n4) return;
    float4 v = ((const float4*)x)[i];
    __half2 h0 = __floats2half2_rn(v.x, v.y);
    __half2 h1 = __floats2half2_rn(v.z, v.w);
    ((__half2*)o)[2 * i]     = h0;
    ((__half2*)o)[2 * i + 1] = h1;
}

// w [E][K][N] fp32 -> o [E][N][K] fp16
__global__ void __launch_bounds__(256) trans_h_kernel(
    const float* __restrict__ w, __half* __restrict__ o, int K, int N)
{
    __shared__ float t[32][33];
    const int e  = blockIdx.z;
    const int k0 = blockIdx.y * 32;
    const int n0 = blockIdx.x * 32;
    const int tx = threadIdx.x & 31;
    const int ty = threadIdx.x >> 5;   // 0..7
    const float* s = w + (size_t)e * K * N;
    #pragma unroll
    for (int i = 0; i < 4; i++)
        t[ty + 8 * i][tx] = s[(size_t)(k0 + ty + 8 * i) * N + n0 + tx];
    __syncthreads();
    __half* d = o + (size_t)e * N * K;
    #pragma unroll
    for (int i = 0; i < 4; i++)
        d[(size_t)(n0 + ty + 8 * i) * K + k0 + tx] = __float2half(t[tx][ty + 8 * i]);
}

// ---------------- launch -----------------------------------------------------
extern "C" void kernel_launch(void* const* d_in, const int* in_sizes, int n_in,
                              void* d_out, int out_size)
{
    const float* x  = (const float*)d_in[0];
    const float* w1 = (const float*)d_in[1];
    const float* w2 = (const float*)d_in[2];
    const float* b1 = (const float*)d_in[3];
    const float* b2 = (const float*)d_in[4];
    float* out = (float*)d_out;

    __half *xh, *w1t, *w2t, *hid;
    cudaGetSymbolAddress((void**)&xh,  g_xh);
    cudaGetSymbolAddress((void**)&w1t, g_w1t);
    cudaGetSymbolAddress((void**)&w2t, g_w2t);
    cudaGetSymbolAddress((void**)&hid, g_hid);

    cudaFuncSetAttribute(gemm_ffn<1>, cudaFuncAttributeMaxDynamicSharedMemorySize, SMEM_GEMM);
    cudaFuncSetAttribute(gemm_ffn<2>, cudaFuncAttributeMaxDynamicSharedMemorySize, SMEM_GEMM);

    // 1) x -> fp16
    size_t n4 = (size_t)NE * NT * DD / 4;
    f2h_kernel<<<(unsigned)((n4 + 255) / 256), 256>>>(x, xh, n4);

    // 2) weights -> K-major fp16
    dim3 t1(HH / 32, DD / 32, NE);
    trans_h_kernel<<<t1, 256>>>(w1, w1t, DD, HH);
    dim3 t2(DD / 32, HH / 32, NE);
    trans_h_kernel<<<t2, 256>>>(w2, w2t, HH, DD);

    // 3) GEMM1: hidden = gelu(x @ w1 + b1)   (fp16 out)
    dim3 g1(HH / BN, NT / BM, NE);
    gemm_ffn<1><<<g1, 256, SMEM_GEMM>>>(xh, w1t, b1, hid, nullptr, NT, HH, DD);

    // 4) GEMM2: out = hidden @ w2 + b2       (fp32 out)
    dim3 g2(DD / BN, NT / BM, NE);
    gemm_ffn<2><<<g2, 256, SMEM_GEMM>>>(hid, w2t, b2, nullptr, out, NT, DD, HH);
}